// round 9
// baseline (speedup 1.0000x reference)
#include <cuda_runtime.h>
#include <cuda_bf16.h>
#include <math.h>

#define D        32
#define HALF     16
#define DP1      33       // D+1
#define RSTRIDE4 16       // float4s per relation row (256 B)
#define MAX_NR   1024
#define MAX_NE   1000000

#define TPB      256

// Per-relation table, one float4 per lane l16=0..15:
//   R4[l16] = (C, S, w1, w2) = (cv*c[l16], cv*s[l16], w[l16], w[l16+16])
__device__ __align__(256) float4 g_relTab[MAX_NR * RSTRIDE4];
// Per-relation boost scalars: (cv*s0, c0, w[0], 0)
__device__ float4 g_boost[MAX_NR];
// Per-entity packed (x0, bias)
__device__ float2 g_sc[MAX_NE];

// ---------------------------------------------------------------------------
// Merged prelude: threads pack entities' (x0,bias) (2 per thread, grid-stride
// flavor); the first NR warps additionally build their relation's table.
// ---------------------------------------------------------------------------
__global__ void prelude(const float* __restrict__ ent,
                        const float* __restrict__ bias,
                        const float* __restrict__ boost,
                        const float* __restrict__ rot,
                        const float* __restrict__ trans,
                        int NE, int NR) {
    const unsigned FULL = 0xFFFFFFFFu;
    int tid  = blockIdx.x * blockDim.x + threadIdx.x;
    int lane = threadIdx.x & 31;
    int wid  = tid >> 5;
    int nthr = gridDim.x * blockDim.x;

    // Two entities per thread (stride = total threads).
    int e0 = tid;
    int e1 = tid + nthr;
    if (e0 < NE)
        g_sc[e0] = make_float2(__ldg(ent + e0 * DP1), __ldg(bias + e0));
    if (e1 < NE)
        g_sc[e1] = make_float2(__ldg(ent + e1 * DP1), __ldg(bias + e1));

    if (wid < NR) {
        int r = wid;
        // v = 0.1*trans; vn = sqrt(max(|v|^2,1e-6)); w = sinh(vn)/vn * v
        float v  = 0.1f * trans[r * D + lane];
        float sq = v * v;
        #pragma unroll
        for (int off = 16; off; off >>= 1)
            sq += __shfl_xor_sync(FULL, sq, off);
        float vn  = sqrtf(fmaxf(sq, 1e-6f));
        float cv  = coshf(vn);
        float svn = sinhf(vn) / vn;
        float w   = svn * v;

        float whi = __shfl_down_sync(FULL, w, 16);   // lane<16: w[lane+16]

        float s = 0.0f, c = 0.0f;
        float rv = (lane < HALF) ? rot[r * D + lane] : 0.0f;
        sincosf(rv, &s, &c);

        if (lane < HALF)
            g_relTab[r * RSTRIDE4 + lane] = make_float4(cv * c, cv * s, w, whi);

        if (lane == 0) {
            float rap = fminf(fmaxf(boost[r * D], -2.0f), 2.0f);
            g_boost[r] = make_float4(cv * sinhf(rap), coshf(rap), w, 0.0f);
        }
    }
}

// ---------------------------------------------------------------------------
// Main: 16-lane groups, 2 samples/iter, 16 iters/warp.
// Lane l16 owns dims (l16, l16+16) of the group's sample. One float4/lane of
// relation data; boost via shuffled per-sample scalars; 6-shfl dual reduction.
// 8 blocks/SM (64 warps) + unroll 8 to maximize loads in flight.
// ---------------------------------------------------------------------------
__global__ __launch_bounds__(TPB, 8) void score16(
        const int*   __restrict__ heads,
        const int*   __restrict__ rels,
        const int*   __restrict__ tails,
        const float* __restrict__ ent,    // [NE,33]
        float*       __restrict__ out,
        int B) {

    const unsigned FULL = 0xFFFFFFFFu;
    const int lane = threadIdx.x & 31;
    const int wid  = (blockIdx.x * TPB + threadIdx.x) >> 5;
    const int i    = wid * 32 + lane;
    const int ic   = min(i, B - 1);
    const int l16  = lane & 15;
    const int gsel = lane & 16;
    const bool hi8 = (l16 & 8) != 0;

    // Coalesced idx loads; random per-own-sample gathers (L2-resident tables).
    const int hi_v = heads[ic];
    const int ri_v = rels [ic];
    const int ti_v = tails[ic];

    float2 sh = g_sc[hi_v];                 // (h0, bias_h)
    float2 st = g_sc[ti_v];                 // (t0, bias_t)
    float4 b4 = __ldg(&g_boost[ri_v]);      // (cv*s0, c0, w0, 0)
    const float bsum   = sh.y + st.y;
    const float t0_own = st.x;
    const float c0_own = b4.y;
    const float bterm  = fmaf(b4.x, sh.x, b4.z);   // cv*s0*h0 + w[0]

    float kss2 = 0.0f, kdt = 0.0f;

    #pragma unroll 8
    for (int it = 0; it < 16; ++it) {
        const int src = gsel | it;          // sample this half-warp processes
        int   hs   = __shfl_sync(FULL, hi_v,  src);
        int   ts   = __shfl_sync(FULL, ti_v,  src);
        int   rs   = __shfl_sync(FULL, ri_v,  src);
        float bts  = __shfl_sync(FULL, bterm, src);
        float c0s  = __shfl_sync(FULL, c0_own, src);

        const float* hr = ent + hs * DP1;
        const float* tr = ent + ts * DP1;
        float a  = __ldcg(hr + 1  + l16);   // h_sp[l16]
        float b  = __ldcg(hr + 17 + l16);   // h_sp[l16+16]
        float ta = __ldcg(tr + 1  + l16);
        float tb = __ldcg(tr + 17 + l16);

        float4 cw = __ldg(&g_relTab[rs * RSTRIDE4 + l16]);  // (C,S,w1,w2)

        float r1   = cw.x * a - cw.y * b;                   // cv * rotated[l16]
        float res1 = (l16 == 0) ? fmaf(c0s, r1, bts)        // boost + trans dim0
                                : (r1 + cw.z);
        float res2 = fmaf(cw.y, a, fmaf(cw.x, b, cw.w));    // cv*rot[l16+16]+w2

        float ss2 = fmaf(res1, res1, res2 * res2);
        float dt  = fmaf(res1, ta,   res2 * tb);

        // 6-shfl dual reduction within each 16-lane half.
        float u = ss2 + __shfl_xor_sync(FULL, ss2, 8);
        float v = dt  + __shfl_xor_sync(FULL, dt,  8);
        float z = hi8 ? v : u;
        #pragma unroll
        for (int off = 1; off < 8; off <<= 1)
            z += __shfl_xor_sync(FULL, z, off);
        float zz = __shfl_xor_sync(FULL, z, 8);
        float ss2_tot = hi8 ? zz : z;
        float dt_tot  = hi8 ? z  : zz;

        bool keep = (l16 == it);            // lane src owns sample src
        kss2 = keep ? ss2_tot : kss2;
        kdt  = keep ? dt_tot  : kdt;
    }

    // Epilogue once per lane on its own sample.
    float ht0   = sqrtf(1.0f + kss2);       // _project time component
    float inner = kdt - ht0 * t0_own;
    float icl   = fmaxf(-inner, 1.0f + 1e-6f);
    float dd    = acoshf(icl);
    if (i < B)
        out[i] = fmaf(-dd, dd, bsum);       // coalesced store
}

// ---------------------------------------------------------------------------
extern "C" void kernel_launch(void* const* d_in, const int* in_sizes, int n_in,
                              void* d_out, int out_size) {
    const int*   heads = (const int*)  d_in[0];
    const int*   rels  = (const int*)  d_in[1];
    const int*   tails = (const int*)  d_in[2];
    const float* ent   = (const float*)d_in[3];
    const float* bw    = (const float*)d_in[4];
    const float* rw    = (const float*)d_in[5];
    const float* tw    = (const float*)d_in[6];
    const float* bias  = (const float*)d_in[7];
    float* out = (float*)d_out;

    int B  = in_sizes[0];
    int NR = in_sizes[4] / D;
    int NE = in_sizes[3] / DP1;

    // Prelude covers ceil(NE/2) threads (2 entities each) and >= NR warps.
    int pthreads = (NE + 1) / 2;
    int pgrid = (pthreads + TPB - 1) / TPB;
    int minw  = (NR * 32 + TPB - 1) / TPB;
    if (pgrid < minw) pgrid = minw;
    prelude<<<pgrid, TPB>>>(ent, bias, bw, rw, tw, NE, NR);

    int nwarps = (B + 31) / 32;
    int grid   = (nwarps * 32 + TPB - 1) / TPB;
    score16<<<grid, TPB>>>(heads, rels, tails, ent, out, B);
}

// round 11
// speedup vs baseline: 1.0813x; 1.0813x over previous
#include <cuda_runtime.h>
#include <cuda_bf16.h>
#include <math.h>

#define D        32
#define HALF     16
#define DP1      33       // D+1
#define RSTRIDE4 16       // float4s per relation row (256 B)
#define MAX_NR   1024
#define MAX_NE   1000000

#define TPB      256

// Per-relation table, one float4 per lane l16=0..15:
//   R4[l16] = (C, S, w1, w2) = (cv*c[l16], cv*s[l16], w[l16], w[l16+16])
__device__ __align__(256) float4 g_relTab[MAX_NR * RSTRIDE4];
// Per-relation boost scalars: (cv*s0, c0, w[0], 0)
__device__ float4 g_boost[MAX_NR];
// Per-entity packed (x0, bias)
__device__ float2 g_sc[MAX_NE];

// ---------------------------------------------------------------------------
// Merged prelude: threads pack entities' (x0,bias) (2 per thread); the first
// NR warps additionally build their relation's table (warp-cooperative).
// ---------------------------------------------------------------------------
__global__ void prelude(const float* __restrict__ ent,
                        const float* __restrict__ bias,
                        const float* __restrict__ boost,
                        const float* __restrict__ rot,
                        const float* __restrict__ trans,
                        int NE, int NR) {
    const unsigned FULL = 0xFFFFFFFFu;
    int tid  = blockIdx.x * blockDim.x + threadIdx.x;
    int lane = threadIdx.x & 31;
    int wid  = tid >> 5;
    int nthr = gridDim.x * blockDim.x;

    int e0 = tid;
    int e1 = tid + nthr;
    if (e0 < NE)
        g_sc[e0] = make_float2(__ldg(ent + e0 * DP1), __ldg(bias + e0));
    if (e1 < NE)
        g_sc[e1] = make_float2(__ldg(ent + e1 * DP1), __ldg(bias + e1));

    if (wid < NR) {
        int r = wid;
        // v = 0.1*trans; vn = sqrt(max(|v|^2,1e-6)); w = sinh(vn)/vn * v
        float v  = 0.1f * trans[r * D + lane];
        float sq = v * v;
        #pragma unroll
        for (int off = 16; off; off >>= 1)
            sq += __shfl_xor_sync(FULL, sq, off);
        float vn  = sqrtf(fmaxf(sq, 1e-6f));
        float cv  = coshf(vn);
        float svn = sinhf(vn) / vn;
        float w   = svn * v;

        float whi = __shfl_down_sync(FULL, w, 16);   // lane<16: w[lane+16]

        float s = 0.0f, c = 0.0f;
        float rv = (lane < HALF) ? rot[r * D + lane] : 0.0f;
        sincosf(rv, &s, &c);

        if (lane < HALF)
            g_relTab[r * RSTRIDE4 + lane] = make_float4(cv * c, cv * s, w, whi);

        if (lane == 0) {
            float rap = fminf(fmaxf(boost[r * D], -2.0f), 2.0f);
            g_boost[r] = make_float4(cv * sinhf(rap), coshf(rap), w, 0.0f);
        }
    }
}

// ---------------------------------------------------------------------------
// Main: 16-lane groups, 2 samples/iter, 16 iters/warp.
// Lane l16 owns dims (l16, l16+16) of the group's sample. Explicit 1-stage
// software pipeline: iteration it+1's entity loads are issued before
// iteration it's reduction, so the shfl chain overlaps the gather latency.
// ---------------------------------------------------------------------------
__global__ __launch_bounds__(TPB, 6) void score16(
        const int*   __restrict__ heads,
        const int*   __restrict__ rels,
        const int*   __restrict__ tails,
        const float* __restrict__ ent,    // [NE,33]
        float*       __restrict__ out,
        int B) {

    const unsigned FULL = 0xFFFFFFFFu;
    const int lane = threadIdx.x & 31;
    const int wid  = (blockIdx.x * TPB + threadIdx.x) >> 5;
    const int i    = wid * 32 + lane;
    const int ic   = min(i, B - 1);
    const int l16  = lane & 15;
    const int gsel = lane & 16;
    const bool hi8 = (l16 & 8) != 0;

    // Coalesced idx loads; random per-own-sample gathers (L2-resident tables).
    const int hi_v = heads[ic];
    const int ri_v = rels [ic];
    const int ti_v = tails[ic];

    float2 sh = g_sc[hi_v];                 // (h0, bias_h)
    float2 st = g_sc[ti_v];                 // (t0, bias_t)
    float4 b4 = __ldg(&g_boost[ri_v]);      // (cv*s0, c0, w0, 0)
    const float bsum   = sh.y + st.y;
    const float t0_own = st.x;
    const float c0_own = b4.y;
    const float bterm  = fmaf(b4.x, sh.x, b4.z);   // cv*s0*h0 + w[0]

    float kss2 = 0.0f, kdt = 0.0f;

    // ---- Pipeline prologue: fetch iteration 0 ----
    int   rs_c, src_c = gsel;
    float a_c, b_c, ta_c, tb_c, bts_c, c0s_c;
    {
        int hs = __shfl_sync(FULL, hi_v, src_c);
        int ts = __shfl_sync(FULL, ti_v, src_c);
        rs_c   = __shfl_sync(FULL, ri_v, src_c);
        bts_c  = __shfl_sync(FULL, bterm,  src_c);
        c0s_c  = __shfl_sync(FULL, c0_own, src_c);
        const float* hr = ent + hs * DP1;
        const float* tr = ent + ts * DP1;
        a_c  = __ldcg(hr + 1  + l16);
        b_c  = __ldcg(hr + 17 + l16);
        ta_c = __ldcg(tr + 1  + l16);
        tb_c = __ldcg(tr + 17 + l16);
    }

    #pragma unroll
    for (int it = 0; it < 16; ++it) {
        // ---- Prefetch iteration it+1 (overlaps with reduction below) ----
        int   rs_n = 0;
        float a_n = 0.f, b_n = 0.f, ta_n = 0.f, tb_n = 0.f, bts_n = 0.f, c0s_n = 0.f;
        if (it < 15) {
            const int src = gsel | (it + 1);
            int hs = __shfl_sync(FULL, hi_v, src);
            int ts = __shfl_sync(FULL, ti_v, src);
            rs_n   = __shfl_sync(FULL, ri_v, src);
            bts_n  = __shfl_sync(FULL, bterm,  src);
            c0s_n  = __shfl_sync(FULL, c0_own, src);
            const float* hr = ent + hs * DP1;
            const float* tr = ent + ts * DP1;
            a_n  = __ldcg(hr + 1  + l16);
            b_n  = __ldcg(hr + 17 + l16);
            ta_n = __ldcg(tr + 1  + l16);
            tb_n = __ldcg(tr + 17 + l16);
        }

        // ---- Compute iteration it ----
        float4 cw = __ldg(&g_relTab[rs_c * RSTRIDE4 + l16]);  // (C,S,w1,w2) L1-hot

        float r1   = cw.x * a_c - cw.y * b_c;                 // cv * rotated[l16]
        float res1 = (l16 == 0) ? fmaf(c0s_c, r1, bts_c)      // boost + trans dim0
                                : (r1 + cw.z);
        float res2 = fmaf(cw.y, a_c, fmaf(cw.x, b_c, cw.w));  // cv*rot[l16+16]+w2

        float ss2 = fmaf(res1, res1, res2 * res2);
        float dt  = fmaf(res1, ta_c, res2 * tb_c);

        // 6-shfl dual reduction within each 16-lane half.
        float u = ss2 + __shfl_xor_sync(FULL, ss2, 8);
        float v = dt  + __shfl_xor_sync(FULL, dt,  8);
        float z = hi8 ? v : u;
        #pragma unroll
        for (int off = 1; off < 8; off <<= 1)
            z += __shfl_xor_sync(FULL, z, off);
        float zz = __shfl_xor_sync(FULL, z, 8);
        float ss2_tot = hi8 ? zz : z;
        float dt_tot  = hi8 ? z  : zz;

        bool keep = (l16 == it);            // lane (gsel|it) owns sample (gsel|it)
        kss2 = keep ? ss2_tot : kss2;
        kdt  = keep ? dt_tot  : kdt;

        // ---- Rotate pipeline registers ----
        a_c = a_n; b_c = b_n; ta_c = ta_n; tb_c = tb_n;
        rs_c = rs_n; bts_c = bts_n; c0s_c = c0s_n;
    }

    // Epilogue once per lane on its own sample.
    float ht0   = sqrtf(1.0f + kss2);       // _project time component
    float inner = kdt - ht0 * t0_own;
    float icl   = fmaxf(-inner, 1.0f + 1e-6f);
    float dd    = acoshf(icl);
    if (i < B)
        out[i] = fmaf(-dd, dd, bsum);       // coalesced store
}

// ---------------------------------------------------------------------------
extern "C" void kernel_launch(void* const* d_in, const int* in_sizes, int n_in,
                              void* d_out, int out_size) {
    const int*   heads = (const int*)  d_in[0];
    const int*   rels  = (const int*)  d_in[1];
    const int*   tails = (const int*)  d_in[2];
    const float* ent   = (const float*)d_in[3];
    const float* bw    = (const float*)d_in[4];
    const float* rw    = (const float*)d_in[5];
    const float* tw    = (const float*)d_in[6];
    const float* bias  = (const float*)d_in[7];
    float* out = (float*)d_out;

    int B  = in_sizes[0];
    int NR = in_sizes[4] / D;
    int NE = in_sizes[3] / DP1;

    int pthreads = (NE + 1) / 2;
    int pgrid = (pthreads + TPB - 1) / TPB;
    int minw  = (NR * 32 + TPB - 1) / TPB;
    if (pgrid < minw) pgrid = minw;
    prelude<<<pgrid, TPB>>>(ent, bias, bw, rw, tw, NE, NR);

    int nwarps = (B + 31) / 32;
    int grid   = (nwarps * 32 + TPB - 1) / TPB;
    score16<<<grid, TPB>>>(heads, rels, tails, ent, out, B);
}